// round 1
// baseline (speedup 1.0000x reference)
#include <cuda_runtime.h>

#define KD 128
#define MAXN 100000
#define MAXE 1600000

// ---------------- device scratch (static allocation; no cudaMalloc) ----------
static __device__ int   g_deg[MAXN];
static __device__ float g_dinv[MAXN];
static __device__ int   g_rowptr[MAXN + 1];
static __device__ int   g_tmp[MAXN];
static __device__ int   g_bsums[128];
static __device__ int   g_fill[MAXN];
static __device__ int   g_csrc[MAXE];
static __device__ float g_cw[MAXE];
static __device__ float g_hA[(size_t)MAXN * KD];
static __device__ float g_hB[(size_t)MAXN * KD];

// ---------------- preprocessing kernels -------------------------------------
__global__ void k_zero(int n) {
    int i = blockIdx.x * blockDim.x + threadIdx.x;
    if (i < n) { g_deg[i] = 0; g_fill[i] = 0; }
}

__global__ void k_deg(const int* __restrict__ dst, int E) {
    int e = blockIdx.x * blockDim.x + threadIdx.x;
    if (e < E) atomicAdd(&g_deg[dst[e]], 1);
}

__global__ void k_dinv(int n) {
    int i = blockIdx.x * blockDim.x + threadIdx.x;
    if (i < n) {
        int d = g_deg[i];
        g_dinv[i] = (d > 0) ? rsqrtf((float)d) : 0.f;
    }
}

// inclusive block scan over deg -> g_tmp, block sums -> g_bsums
__global__ void k_scan1(int n) {
    __shared__ int s[1024];
    int t = threadIdx.x;
    int i = blockIdx.x * 1024 + t;
    int v = (i < n) ? g_deg[i] : 0;
    s[t] = v;
    __syncthreads();
    for (int off = 1; off < 1024; off <<= 1) {
        int x = (t >= off) ? s[t - off] : 0;
        __syncthreads();
        s[t] += x;
        __syncthreads();
    }
    if (i < n) g_tmp[i] = s[t];
    if (t == 1023) g_bsums[blockIdx.x] = s[t];
}

// exclusive scan of block sums (nb <= 128), in place
__global__ void k_scan2(int nb) {
    __shared__ int s[128];
    int t = threadIdx.x;
    int v = (t < nb) ? g_bsums[t] : 0;
    s[t] = v;
    __syncthreads();
    for (int off = 1; off < 128; off <<= 1) {
        int x = (t >= off) ? s[t - off] : 0;
        __syncthreads();
        s[t] += x;
        __syncthreads();
    }
    if (t < nb) g_bsums[t] = s[t] - v;   // exclusive offset
}

__global__ void k_scan3(int n) {
    int i = blockIdx.x * blockDim.x + threadIdx.x;
    if (i < n) {
        g_rowptr[i + 1] = g_tmp[i] + g_bsums[i >> 10];
        if (i == 0) g_rowptr[0] = 0;
    }
}

__global__ void k_fill(const int* __restrict__ src, const int* __restrict__ dst, int E) {
    int e = blockIdx.x * blockDim.x + threadIdx.x;
    if (e < E) {
        int s = src[e], d = dst[e];
        int pos = g_rowptr[d] + atomicAdd(&g_fill[d], 1);
        g_csrc[pos] = s;
        g_cw[pos]   = g_dinv[s] * g_dinv[d];
    }
}

// ---------------- dense transform: Y[n][O] = X[n][128] @ W[O][128]^T --------
// 256 threads, tile M=128 rows, full K=128 and full O resident in smem.
// thread (tx = t%16, ty = t/16) computes rows ty*8..ty*8+7, outs tx*TO..+TO-1.
template <int O>
__global__ void k_gemm(const float* __restrict__ X, const float* __restrict__ W,
                       float* __restrict__ Y, int n) {
    constexpr int XP = 132;       // padded row stride for xs (k-major)
    constexpr int OP = O + 4;     // padded row stride for ws (k-major)
    constexpr int TO = O / 16;    // outs per thread (8 or 4)
    extern __shared__ float sm[];
    float* xs = sm;               // xs[k*XP + m]
    float* ws = sm + 128 * XP;    // ws[k*OP + o]

    const int t  = threadIdx.x;
    const int m0 = blockIdx.x * 128;

    // load X tile (128 rows x 128 k), transpose into xs[k][m]
    for (int idx = t; idx < 128 * 32; idx += 256) {
        int row = idx >> 5, k4 = idx & 31;
        float4 v = make_float4(0.f, 0.f, 0.f, 0.f);
        if (m0 + row < n)
            v = ((const float4*)X)[(size_t)(m0 + row) * 32 + k4];
        xs[(4 * k4 + 0) * XP + row] = v.x;
        xs[(4 * k4 + 1) * XP + row] = v.y;
        xs[(4 * k4 + 2) * XP + row] = v.z;
        xs[(4 * k4 + 3) * XP + row] = v.w;
    }
    // load W (O rows x 128 k), transpose into ws[k][o]
    for (int idx = t; idx < O * 32; idx += 256) {
        int o = idx >> 5, k4 = idx & 31;
        float4 v = ((const float4*)W)[o * 32 + k4];
        ws[(4 * k4 + 0) * OP + o] = v.x;
        ws[(4 * k4 + 1) * OP + o] = v.y;
        ws[(4 * k4 + 2) * OP + o] = v.z;
        ws[(4 * k4 + 3) * OP + o] = v.w;
    }
    __syncthreads();

    const int tx = t & 15, ty = t >> 4;
    float acc[8][TO];
#pragma unroll
    for (int i = 0; i < 8; i++)
#pragma unroll
        for (int j = 0; j < TO; j++) acc[i][j] = 0.f;

#pragma unroll 4
    for (int k = 0; k < 128; k++) {
        float a[8];
        float4 a0 = *(const float4*)&xs[k * XP + ty * 8];
        float4 a1 = *(const float4*)&xs[k * XP + ty * 8 + 4];
        a[0] = a0.x; a[1] = a0.y; a[2] = a0.z; a[3] = a0.w;
        a[4] = a1.x; a[5] = a1.y; a[6] = a1.z; a[7] = a1.w;
        float b[TO];
        float4 b0 = *(const float4*)&ws[k * OP + tx * TO];
        b[0] = b0.x; b[1] = b0.y; b[2] = b0.z; b[3] = b0.w;
        if (TO == 8) {
            float4 b1 = *(const float4*)&ws[k * OP + tx * TO + 4];
            b[4] = b1.x; b[5] = b1.y; b[6] = b1.z; b[7] = b1.w;
        }
#pragma unroll
        for (int i = 0; i < 8; i++)
#pragma unroll
            for (int j = 0; j < TO; j++)
                acc[i][j] = fmaf(a[i], b[j], acc[i][j]);
    }

#pragma unroll
    for (int i = 0; i < 8; i++) {
        int row = m0 + ty * 8 + i;
        if (row < n) {
            float* yr = &Y[(size_t)row * O + tx * TO];
#pragma unroll
            for (int j4 = 0; j4 < TO; j4 += 4) {
                float4 v = make_float4(acc[i][j4], acc[i][j4 + 1],
                                       acc[i][j4 + 2], acc[i][j4 + 3]);
                *(float4*)(yr + j4) = v;
            }
        }
    }
}

// ---------------- aggregation: out[d] = sum_e w_e * h[src_e] + b (relu?) ----
// one warp per destination node, D=128 channels -> one float4 per lane
__global__ void k_agg128(const float* __restrict__ h, const float* __restrict__ bias,
                         float* __restrict__ out, int n, int relu) {
    int w    = (blockIdx.x * blockDim.x + threadIdx.x) >> 5;
    int lane = threadIdx.x & 31;
    if (w >= n) return;
    const float4* hv = (const float4*)h;
    float4 acc = make_float4(0.f, 0.f, 0.f, 0.f);
    int beg = g_rowptr[w], end = g_rowptr[w + 1];
#pragma unroll 4
    for (int e = beg; e < end; e++) {
        int   s  = g_csrc[e];
        float ww = g_cw[e];
        float4 v = hv[(size_t)s * 32 + lane];
        acc.x = fmaf(ww, v.x, acc.x);
        acc.y = fmaf(ww, v.y, acc.y);
        acc.z = fmaf(ww, v.z, acc.z);
        acc.w = fmaf(ww, v.w, acc.w);
    }
    float4 bb = ((const float4*)bias)[lane];
    acc.x += bb.x; acc.y += bb.y; acc.z += bb.z; acc.w += bb.w;
    if (relu) {
        acc.x = fmaxf(acc.x, 0.f); acc.y = fmaxf(acc.y, 0.f);
        acc.z = fmaxf(acc.z, 0.f); acc.w = fmaxf(acc.w, 0.f);
    }
    ((float4*)out)[(size_t)w * 32 + lane] = acc;
}

// D=64 channels -> one float2 per lane
__global__ void k_agg64(const float* __restrict__ h, const float* __restrict__ bias,
                        float* __restrict__ out, int n, int relu) {
    int w    = (blockIdx.x * blockDim.x + threadIdx.x) >> 5;
    int lane = threadIdx.x & 31;
    if (w >= n) return;
    const float2* hv = (const float2*)h;
    float2 acc = make_float2(0.f, 0.f);
    int beg = g_rowptr[w], end = g_rowptr[w + 1];
#pragma unroll 4
    for (int e = beg; e < end; e++) {
        int   s  = g_csrc[e];
        float ww = g_cw[e];
        float2 v = hv[(size_t)s * 32 + lane];
        acc.x = fmaf(ww, v.x, acc.x);
        acc.y = fmaf(ww, v.y, acc.y);
    }
    float2 bb = ((const float2*)bias)[lane];
    acc.x += bb.x; acc.y += bb.y;
    if (relu) { acc.x = fmaxf(acc.x, 0.f); acc.y = fmaxf(acc.y, 0.f); }
    ((float2*)out)[(size_t)w * 32 + lane] = acc;
}

// ---------------- launch ------------------------------------------------------
extern "C" void kernel_launch(void* const* d_in, const int* in_sizes, int n_in,
                              void* d_out, int out_size) {
    const float* x  = (const float*)d_in[0];
    const int*   ei = (const int*)d_in[1];
    const float* W1 = (const float*)d_in[2];
    const float* b1 = (const float*)d_in[3];
    const float* W2 = (const float*)d_in[4];
    const float* b2 = (const float*)d_in[5];
    const float* W3 = (const float*)d_in[6];
    const float* b3 = (const float*)d_in[7];
    const float* W4 = (const float*)d_in[8];
    const float* b4 = (const float*)d_in[9];

    const int n = in_sizes[0] / KD;       // 100000
    const int E = in_sizes[1] / 2;        // 1600000
    const int* src = ei;
    const int* dst = ei + E;

    float *hA, *hB;
    cudaGetSymbolAddress((void**)&hA, g_hA);
    cudaGetSymbolAddress((void**)&hB, g_hB);

    const int smem128 = (128 * 132 + 128 * (128 + 4)) * 4;  // 135168
    const int smem64  = (128 * 132 + 128 * (64 + 4)) * 4;   // 102400
    cudaFuncSetAttribute(k_gemm<128>, cudaFuncAttributeMaxDynamicSharedMemorySize, smem128);
    cudaFuncSetAttribute(k_gemm<64>,  cudaFuncAttributeMaxDynamicSharedMemorySize, smem64);

    const int TB = 256;
    int nb_n = (n + TB - 1) / TB;
    int nb_e = (E + TB - 1) / TB;
    int nb_scan = (n + 1023) / 1024;           // <= 128
    int nb_gemm = (n + 127) / 128;
    int nb_agg  = (n * 32 + TB - 1) / TB;      // one warp per node

    // --- build normalization + CSR (by dst) ---
    k_zero <<<nb_n, TB>>>(n);
    k_deg  <<<nb_e, TB>>>(dst, E);
    k_dinv <<<nb_n, TB>>>(n);
    k_scan1<<<nb_scan, 1024>>>(n);
    k_scan2<<<1, 128>>>(nb_scan);
    k_scan3<<<nb_n, TB>>>(n);
    k_fill <<<nb_e, TB>>>(src, dst, E);

    // --- layer 1 ---
    k_gemm<128><<<nb_gemm, 256, smem128>>>(x, W1, hA, n);
    k_agg128   <<<nb_agg, TB>>>(hA, b1, hB, n, 1);
    // --- layer 2 ---
    k_gemm<128><<<nb_gemm, 256, smem128>>>(hB, W2, hA, n);
    k_agg128   <<<nb_agg, TB>>>(hA, b2, hB, n, 1);
    // --- layer 3 ---
    k_gemm<128><<<nb_gemm, 256, smem128>>>(hB, W3, hA, n);
    k_agg128   <<<nb_agg, TB>>>(hA, b3, hB, n, 1);
    // --- layer 4 (out dim 64, no relu, straight to d_out) ---
    k_gemm<64> <<<nb_gemm, 256, smem64>>>(hB, W4, hA, n);
    k_agg64    <<<nb_agg, TB>>>(hA, b4, (float*)d_out, n, 0);
}

// round 3
// speedup vs baseline: 1.3577x; 1.3577x over previous
#include <cuda_runtime.h>
#include <cstdint>

#define KD 128
#define MAXN 100000
#define MAXE 1600000

// ---------------- device scratch (static; no cudaMalloc) --------------------
static __device__ int   g_deg[MAXN];
static __device__ float g_dinv[MAXN];
static __device__ int   g_rowptr[MAXN + 1];
static __device__ int   g_tmp[MAXN];
static __device__ int   g_bsums[128];
static __device__ int   g_fill[MAXN];
static __device__ int2  g_cedge[MAXE];          // (src, weight-bits)
static __device__ float g_hA[(size_t)MAXN * KD];
static __device__ float g_hB[(size_t)MAXN * KD];

// ---------------- preprocessing kernels -------------------------------------
__global__ void k_zero(int n) {
    int i = blockIdx.x * blockDim.x + threadIdx.x;
    if (i < n) { g_deg[i] = 0; g_fill[i] = 0; }
}
__global__ void k_deg(const int* __restrict__ dst, int E) {
    int e = blockIdx.x * blockDim.x + threadIdx.x;
    if (e < E) atomicAdd(&g_deg[dst[e]], 1);
}
__global__ void k_dinv(int n) {
    int i = blockIdx.x * blockDim.x + threadIdx.x;
    if (i < n) {
        int d = g_deg[i];
        g_dinv[i] = (d > 0) ? rsqrtf((float)d) : 0.f;
    }
}
__global__ void k_scan1(int n) {
    __shared__ int s[1024];
    int t = threadIdx.x;
    int i = blockIdx.x * 1024 + t;
    int v = (i < n) ? g_deg[i] : 0;
    s[t] = v;
    __syncthreads();
    for (int off = 1; off < 1024; off <<= 1) {
        int x = (t >= off) ? s[t - off] : 0;
        __syncthreads();
        s[t] += x;
        __syncthreads();
    }
    if (i < n) g_tmp[i] = s[t];
    if (t == 1023) g_bsums[blockIdx.x] = s[t];
}
__global__ void k_scan2(int nb) {
    __shared__ int s[128];
    int t = threadIdx.x;
    int v = (t < nb) ? g_bsums[t] : 0;
    s[t] = v;
    __syncthreads();
    for (int off = 1; off < 128; off <<= 1) {
        int x = (t >= off) ? s[t - off] : 0;
        __syncthreads();
        s[t] += x;
        __syncthreads();
    }
    if (t < nb) g_bsums[t] = s[t] - v;
}
__global__ void k_scan3(int n) {
    int i = blockIdx.x * blockDim.x + threadIdx.x;
    if (i < n) {
        g_rowptr[i + 1] = g_tmp[i] + g_bsums[i >> 10];
        if (i == 0) g_rowptr[0] = 0;
    }
}
__global__ void k_fill(const int* __restrict__ src, const int* __restrict__ dst, int E) {
    int e = blockIdx.x * blockDim.x + threadIdx.x;
    if (e < E) {
        int s = src[e], d = dst[e];
        int pos = g_rowptr[d] + atomicAdd(&g_fill[d], 1);
        g_cedge[pos] = make_int2(s, __float_as_int(g_dinv[s] * g_dinv[d]));
    }
}

// ---------------- tf32 mma.sync GEMM: Y[n][O] = X[n][128] @ W[O][128]^T -----
__device__ __forceinline__ uint32_t f2tf32(float f) {
    uint32_t r;
    asm("cvt.rna.tf32.f32 %0, %1;" : "=r"(r) : "f"(f));
    return r;
}
__device__ __forceinline__ void mma_tf32(float& d0, float& d1, float& d2, float& d3,
                                         uint32_t a0, uint32_t a1, uint32_t a2, uint32_t a3,
                                         uint32_t b0, uint32_t b1) {
    asm volatile(
        "mma.sync.aligned.m16n8k8.row.col.f32.tf32.tf32.f32 "
        "{%0,%1,%2,%3}, {%4,%5,%6,%7}, {%8,%9}, {%0,%1,%2,%3};"
        : "+f"(d0), "+f"(d1), "+f"(d2), "+f"(d3)
        : "r"(a0), "r"(a1), "r"(a2), "r"(a3), "r"(b0), "r"(b1));
}

// 256 threads = 8 warps laid out 4(m) x 2(n). CTA tile: 128 x O, K=128 resident.
// Warp tile: 32 x (O/2).  m16n8k8 fragments loaded by scalar LDS (conflict-free
// with 132-float row padding: bank = (gid*4 + ctg) % 32, all lanes distinct).
template <int O>
__global__ void __launch_bounds__(256, 1) k_mma(const float* __restrict__ X,
                                                const float* __restrict__ W,
                                                float* __restrict__ Y, int n) {
    constexpr int LDA = 132;
    constexpr int NT  = (O / 2) / 8;     // n-tiles per warp: 8 (O=128) or 4 (O=64)
    extern __shared__ uint32_t sm[];
    uint32_t* As = sm;                   // [128][LDA] tf32 bits
    uint32_t* Bs = sm + 128 * LDA;       // [O][LDA]

    const int tid = threadIdx.x;
    const int m0  = blockIdx.x * 128;

    // load X tile (tf32-converted)
    const float4* X4 = (const float4*)X;
    for (int idx = tid; idx < 128 * 32; idx += 256) {
        int row = idx >> 5, q = idx & 31;
        float4 v = make_float4(0.f, 0.f, 0.f, 0.f);
        if (m0 + row < n) v = X4[(size_t)(m0 + row) * 32 + q];
        uint4 u = make_uint4(f2tf32(v.x), f2tf32(v.y), f2tf32(v.z), f2tf32(v.w));
        *(uint4*)&As[row * LDA + q * 4] = u;
    }
    // load W (O x 128)
    const float4* W4 = (const float4*)W;
    for (int idx = tid; idx < O * 32; idx += 256) {
        int row = idx >> 5, q = idx & 31;
        float4 v = W4[row * 32 + q];
        uint4 u = make_uint4(f2tf32(v.x), f2tf32(v.y), f2tf32(v.z), f2tf32(v.w));
        *(uint4*)&Bs[row * LDA + q * 4] = u;
    }
    __syncthreads();

    const int wid  = tid >> 5;
    const int lane = tid & 31;
    const int wm   = (wid & 3) * 32;          // warp m offset
    const int wn   = (wid >> 2) * (O / 2);    // warp n offset
    const int gid  = lane >> 2;               // 0..7
    const int ctg  = lane & 3;                // 0..3

    float acc[2][NT][4];
#pragma unroll
    for (int i = 0; i < 2; i++)
#pragma unroll
        for (int j = 0; j < NT; j++)
#pragma unroll
            for (int c = 0; c < 4; c++) acc[i][j][c] = 0.f;

#pragma unroll
    for (int ks = 0; ks < 16; ks++) {
        const int k0 = ks * 8;
        uint32_t a[2][4];
#pragma unroll
        for (int mt = 0; mt < 2; mt++) {
            const uint32_t* ar = &As[(wm + mt * 16 + gid) * LDA + k0 + ctg];
            a[mt][0] = ar[0];
            a[mt][1] = ar[8 * LDA];
            a[mt][2] = ar[4];
            a[mt][3] = ar[8 * LDA + 4];
        }
#pragma unroll
        for (int nt = 0; nt < NT; nt++) {
            const uint32_t* br = &Bs[(wn + nt * 8 + gid) * LDA + k0 + ctg];
            uint32_t b0 = br[0], b1 = br[4];
#pragma unroll
            for (int mt = 0; mt < 2; mt++)
                mma_tf32(acc[mt][nt][0], acc[mt][nt][1], acc[mt][nt][2], acc[mt][nt][3],
                         a[mt][0], a[mt][1], a[mt][2], a[mt][3], b0, b1);
        }
    }

    // epilogue: c0,c1 -> row gid, cols 2*ctg..+1 ; c2,c3 -> row gid+8
#pragma unroll
    for (int mt = 0; mt < 2; mt++) {
        int r0 = m0 + wm + mt * 16 + gid;
        int r1 = r0 + 8;
#pragma unroll
        for (int nt = 0; nt < NT; nt++) {
            int col = wn + nt * 8 + 2 * ctg;
            if (r0 < n)
                *(float2*)&Y[(size_t)r0 * O + col] = make_float2(acc[mt][nt][0], acc[mt][nt][1]);
            if (r1 < n)
                *(float2*)&Y[(size_t)r1 * O + col] = make_float2(acc[mt][nt][2], acc[mt][nt][3]);
        }
    }
}

// ---------------- aggregation: out[d] = sum_e w_e * h[src_e] + b (relu?) ----
__global__ void k_agg128(const float* __restrict__ h, const float* __restrict__ bias,
                         float* __restrict__ out, int n, int relu) {
    int w    = (blockIdx.x * blockDim.x + threadIdx.x) >> 5;
    int lane = threadIdx.x & 31;
    if (w >= n) return;
    const float4* hv = (const float4*)h;
    float4 acc = make_float4(0.f, 0.f, 0.f, 0.f);
    int beg = g_rowptr[w], end = g_rowptr[w + 1];
    int e = beg;
    for (; e + 8 <= end; e += 8) {
        int2 p[8];
#pragma unroll
        for (int j = 0; j < 8; j++) p[j] = g_cedge[e + j];
#pragma unroll
        for (int j = 0; j < 8; j++) {
            float  ww = __int_as_float(p[j].y);
            float4 v  = hv[(size_t)p[j].x * 32 + lane];
            acc.x = fmaf(ww, v.x, acc.x);
            acc.y = fmaf(ww, v.y, acc.y);
            acc.z = fmaf(ww, v.z, acc.z);
            acc.w = fmaf(ww, v.w, acc.w);
        }
    }
    for (; e < end; e++) {
        int2 p = g_cedge[e];
        float  ww = __int_as_float(p.y);
        float4 v  = hv[(size_t)p.x * 32 + lane];
        acc.x = fmaf(ww, v.x, acc.x);
        acc.y = fmaf(ww, v.y, acc.y);
        acc.z = fmaf(ww, v.z, acc.z);
        acc.w = fmaf(ww, v.w, acc.w);
    }
    float4 bb = ((const float4*)bias)[lane];
    acc.x += bb.x; acc.y += bb.y; acc.z += bb.z; acc.w += bb.w;
    if (relu) {
        acc.x = fmaxf(acc.x, 0.f); acc.y = fmaxf(acc.y, 0.f);
        acc.z = fmaxf(acc.z, 0.f); acc.w = fmaxf(acc.w, 0.f);
    }
    ((float4*)out)[(size_t)w * 32 + lane] = acc;
}

__global__ void k_agg64(const float* __restrict__ h, const float* __restrict__ bias,
                        float* __restrict__ out, int n, int relu) {
    int w    = (blockIdx.x * blockDim.x + threadIdx.x) >> 5;
    int lane = threadIdx.x & 31;
    if (w >= n) return;
    const float2* hv = (const float2*)h;
    float2 acc = make_float2(0.f, 0.f);
    int beg = g_rowptr[w], end = g_rowptr[w + 1];
    int e = beg;
    for (; e + 8 <= end; e += 8) {
        int2 p[8];
#pragma unroll
        for (int j = 0; j < 8; j++) p[j] = g_cedge[e + j];
#pragma unroll
        for (int j = 0; j < 8; j++) {
            float  ww = __int_as_float(p[j].y);
            float2 v  = hv[(size_t)p[j].x * 32 + lane];
            acc.x = fmaf(ww, v.x, acc.x);
            acc.y = fmaf(ww, v.y, acc.y);
        }
    }
    for (; e < end; e++) {
        int2 p = g_cedge[e];
        float  ww = __int_as_float(p.y);
        float2 v  = hv[(size_t)p.x * 32 + lane];
        acc.x = fmaf(ww, v.x, acc.x);
        acc.y = fmaf(ww, v.y, acc.y);
    }
    float2 bb = ((const float2*)bias)[lane];
    acc.x += bb.x; acc.y += bb.y;
    if (relu) { acc.x = fmaxf(acc.x, 0.f); acc.y = fmaxf(acc.y, 0.f); }
    ((float2*)out)[(size_t)w * 32 + lane] = acc;
}

// ---------------- launch ------------------------------------------------------
extern "C" void kernel_launch(void* const* d_in, const int* in_sizes, int n_in,
                              void* d_out, int out_size) {
    const float* x  = (const float*)d_in[0];
    const int*   ei = (const int*)d_in[1];
    const float* W1 = (const float*)d_in[2];
    const float* b1 = (const float*)d_in[3];
    const float* W2 = (const float*)d_in[4];
    const float* b2 = (const float*)d_in[5];
    const float* W3 = (const float*)d_in[6];
    const float* b3 = (const float*)d_in[7];
    const float* W4 = (const float*)d_in[8];
    const float* b4 = (const float*)d_in[9];

    const int n = in_sizes[0] / KD;       // 100000
    const int E = in_sizes[1] / 2;        // 1600000
    const int* src = ei;
    const int* dst = ei + E;

    float *hA, *hB;
    cudaGetSymbolAddress((void**)&hA, g_hA);
    cudaGetSymbolAddress((void**)&hB, g_hB);

    const int smem128 = (128 + 128) * 132 * 4;   // 135168
    const int smem64  = (128 + 64) * 132 * 4;    // 101376
    cudaFuncSetAttribute(k_mma<128>, cudaFuncAttributeMaxDynamicSharedMemorySize, smem128);
    cudaFuncSetAttribute(k_mma<64>,  cudaFuncAttributeMaxDynamicSharedMemorySize, smem64);

    const int TB = 256;
    int nb_n = (n + TB - 1) / TB;
    int nb_e = (E + TB - 1) / TB;
    int nb_scan = (n + 1023) / 1024;           // <= 128
    int nb_gemm = (n + 127) / 128;
    int nb_agg  = (n * 32 + TB - 1) / TB;      // one warp per node

    // --- build normalization + CSR (by dst) ---
    k_zero <<<nb_n, TB>>>(n);
    k_deg  <<<nb_e, TB>>>(dst, E);
    k_dinv <<<nb_n, TB>>>(n);
    k_scan1<<<nb_scan, 1024>>>(n);
    k_scan2<<<1, 128>>>(nb_scan);
    k_scan3<<<nb_n, TB>>>(n);
    k_fill <<<nb_e, TB>>>(src, dst, E);

    // --- layer 1 ---
    k_mma<128><<<nb_gemm, 256, smem128>>>(x, W1, hA, n);
    k_agg128  <<<nb_agg, TB>>>(hA, b1, hB, n, 1);
    // --- layer 2 ---
    k_mma<128><<<nb_gemm, 256, smem128>>>(hB, W2, hA, n);
    k_agg128  <<<nb_agg, TB>>>(hA, b2, hB, n, 1);
    // --- layer 3 ---
    k_mma<128><<<nb_gemm, 256, smem128>>>(hB, W3, hA, n);
    k_agg128  <<<nb_agg, TB>>>(hA, b3, hB, n, 1);
    // --- layer 4 (out dim 64, no relu, straight to d_out) ---
    k_mma<64> <<<nb_gemm, 256, smem64>>>(hB, W4, hA, n);
    k_agg64   <<<nb_agg, TB>>>(hA, b4, (float*)d_out, n, 0);
}

// round 5
// speedup vs baseline: 1.8448x; 1.3588x over previous
#include <cuda_runtime.h>
#include <cstdint>

#define KD 128
#define MAXN 100000
#define MAXE 1600000

// ---------------- device scratch (static; no cudaMalloc) --------------------
static __device__ int   g_deg[MAXN];
static __device__ float g_dinv[MAXN];
static __device__ int   g_rowptr[MAXN + 1];
static __device__ int   g_tmp[MAXN];
static __device__ int   g_bsums[128];
static __device__ int   g_fill[MAXN];
static __device__ int2  g_cedge[MAXE];          // (src, weight-bits)
static __device__ float g_hA[(size_t)MAXN * KD];
static __device__ float g_hB[(size_t)MAXN * KD];
static __device__ float g_Wr[3 * 128 * 128 + 64 * 128];   // tf32-rounded W1..W4

// ---------------- tf32 helpers ----------------------------------------------
__device__ __forceinline__ float rna_tf32(float f) {
    uint32_t r;
    asm("cvt.rna.tf32.f32 %0, %1;" : "=r"(r) : "f"(f));
    return __uint_as_float(r);
}

// ---------------- cp.async helpers ------------------------------------------
__device__ __forceinline__ void cpa16(uint32_t saddr, const void* gaddr, uint32_t ssz) {
    asm volatile("cp.async.cg.shared.global [%0], [%1], 16, %2;"
                 :: "r"(saddr), "l"(gaddr), "r"(ssz) : "memory");
}
#define CP_COMMIT()  asm volatile("cp.async.commit_group;" ::: "memory")
#define CP_WAIT1()   asm volatile("cp.async.wait_group 1;" ::: "memory")
#define CP_WAIT0()   asm volatile("cp.async.wait_group 0;" ::: "memory")

// ---------------- preprocessing kernels -------------------------------------
__global__ void k_zero(int n) {
    int i = blockIdx.x * blockDim.x + threadIdx.x;
    if (i < n) { g_deg[i] = 0; g_fill[i] = 0; }
}
__global__ void k_deg(const int* __restrict__ dst, int E) {
    int e = blockIdx.x * blockDim.x + threadIdx.x;
    if (e < E) atomicAdd(&g_deg[dst[e]], 1);
}
__global__ void k_scan1(int n) {
    __shared__ int s[1024];
    int t = threadIdx.x;
    int i = blockIdx.x * 1024 + t;
    int v = (i < n) ? g_deg[i] : 0;
    s[t] = v;
    __syncthreads();
    for (int off = 1; off < 1024; off <<= 1) {
        int x = (t >= off) ? s[t - off] : 0;
        __syncthreads();
        s[t] += x;
        __syncthreads();
    }
    if (i < n) g_tmp[i] = s[t];
    if (t == 1023) g_bsums[blockIdx.x] = s[t];
}
__global__ void k_scan2(int nb) {
    __shared__ int s[128];
    int t = threadIdx.x;
    int v = (t < nb) ? g_bsums[t] : 0;
    s[t] = v;
    __syncthreads();
    for (int off = 1; off < 128; off <<= 1) {
        int x = (t >= off) ? s[t - off] : 0;
        __syncthreads();
        s[t] += x;
        __syncthreads();
    }
    if (t < nb) g_bsums[t] = s[t] - v;
}
__global__ void k_scan3(int n) {            // also computes dinv
    int i = blockIdx.x * blockDim.x + threadIdx.x;
    if (i < n) {
        g_rowptr[i + 1] = g_tmp[i] + g_bsums[i >> 10];
        if (i == 0) g_rowptr[0] = 0;
        int d = g_deg[i];
        g_dinv[i] = (d > 0) ? rsqrtf((float)d) : 0.f;
    }
}
__global__ void k_fill(const int* __restrict__ src, const int* __restrict__ dst, int E) {
    int e = blockIdx.x * blockDim.x + threadIdx.x;
    if (e < E) {
        int s = src[e], d = dst[e];
        int pos = g_rowptr[d] + atomicAdd(&g_fill[d], 1);
        g_cedge[pos] = make_int2(s, __float_as_int(g_dinv[s] * g_dinv[d]));
    }
}

// elementwise tf32 rounding pass (vectorized)
__global__ void k_round(const float* __restrict__ in, float* __restrict__ out, int m4) {
    int i = blockIdx.x * blockDim.x + threadIdx.x;
    if (i < m4) {
        float4 v = ((const float4*)in)[i];
        v.x = rna_tf32(v.x); v.y = rna_tf32(v.y);
        v.z = rna_tf32(v.z); v.w = rna_tf32(v.w);
        ((float4*)out)[i] = v;
    }
}

// round all 4 weight matrices into g_Wr
__global__ void k_round_w(const float* __restrict__ W1, const float* __restrict__ W2,
                          const float* __restrict__ W3, const float* __restrict__ W4) {
    int i = blockIdx.x * blockDim.x + threadIdx.x;     // float4 index
    const int S = 128 * 128 / 4;                       // 4096 float4 per 128x128
    const float4* src;
    int off;
    if      (i < S)     { src = (const float4*)W1; off = 0;     }
    else if (i < 2 * S) { src = (const float4*)W2; off = S;     i -= S; }
    else if (i < 3 * S) { src = (const float4*)W3; off = 2 * S; i -= 2 * S; }
    else if (i < 3 * S + S / 2) { src = (const float4*)W4; off = 3 * S; i -= 3 * S; }
    else return;
    float4 v = src[i];
    v.x = rna_tf32(v.x); v.y = rna_tf32(v.y);
    v.z = rna_tf32(v.z); v.w = rna_tf32(v.w);
    ((float4*)g_Wr)[off + i] = v;
}

// ---------------- tf32 mma.sync GEMM, cp.async double-buffered --------------
// inputs X and W are ALREADY tf32-rounded (RNA) by the producers.
__device__ __forceinline__ void mma_tf32(float& d0, float& d1, float& d2, float& d3,
                                         uint32_t a0, uint32_t a1, uint32_t a2, uint32_t a3,
                                         uint32_t b0, uint32_t b1) {
    asm volatile(
        "mma.sync.aligned.m16n8k8.row.col.f32.tf32.tf32.f32 "
        "{%0,%1,%2,%3}, {%4,%5,%6,%7}, {%8,%9}, {%0,%1,%2,%3};"
        : "+f"(d0), "+f"(d1), "+f"(d2), "+f"(d3)
        : "r"(a0), "r"(a1), "r"(a2), "r"(a3), "r"(b0), "r"(b1));
}

template <int O>
__global__ void __launch_bounds__(256, 2) k_mma(const float* __restrict__ X,
                                                const float* __restrict__ W,
                                                float* __restrict__ Y, int n) {
    constexpr int SK = 36;               // 32 + 4 pad
    constexpr int NT = (O / 2) / 8;
    extern __shared__ float sm[];
    float* As = sm;                      // [2][128*SK]
    float* Bs = sm + 2 * 128 * SK;       // [2][O*SK]
    const uint32_t sA = (uint32_t)__cvta_generic_to_shared(As);
    const uint32_t sB = (uint32_t)__cvta_generic_to_shared(Bs);

    const int tid = threadIdx.x;
    const int m0  = blockIdx.x * 128;

    auto load_chunk = [&](int c, int buf) {
        for (int idx = tid; idx < 128 * 8; idx += 256) {
            int row = idx >> 3, seg = idx & 7;
            uint32_t sa = sA + (uint32_t)((buf * 128 * SK + row * SK + seg * 4) * 4);
            int grow = (m0 + row < n) ? (m0 + row) : 0;
            const float* g = X + (size_t)grow * 128 + c * 32 + seg * 4;
            cpa16(sa, g, (m0 + row < n) ? 16u : 0u);
        }
        for (int idx = tid; idx < O * 8; idx += 256) {
            int row = idx >> 3, seg = idx & 7;
            uint32_t sa = sB + (uint32_t)((buf * O * SK + row * SK + seg * 4) * 4);
            const float* g = W + (size_t)row * 128 + c * 32 + seg * 4;
            cpa16(sa, g, 16u);
        }
        CP_COMMIT();
    };

    const int wid  = tid >> 5;
    const int lane = tid & 31;
    const int wm   = (wid & 3) * 32;
    const int wn   = (wid >> 2) * (O / 2);
    const int gid  = lane >> 2;
    const int ctg  = lane & 3;

    float acc[2][NT][4];
#pragma unroll
    for (int i = 0; i < 2; i++)
#pragma unroll
        for (int j = 0; j < NT; j++)
#pragma unroll
            for (int c = 0; c < 4; c++) acc[i][j][c] = 0.f;

    load_chunk(0, 0);

#pragma unroll
    for (int c = 0; c < 4; c++) {
        if (c < 3) { load_chunk(c + 1, (c + 1) & 1); CP_WAIT1(); }
        else       { CP_WAIT0(); }
        __syncthreads();

        const uint32_t* Ab = (const uint32_t*)(As + (c & 1) * 128 * SK);
        const uint32_t* Bb = (const uint32_t*)(Bs + (c & 1) * O * SK);
#pragma unroll
        for (int kk = 0; kk < 32; kk += 8) {
            uint32_t a[2][4];
#pragma unroll
            for (int mt = 0; mt < 2; mt++) {
                const uint32_t* ar = &Ab[(wm + mt * 16 + gid) * SK + kk + ctg];
                a[mt][0] = ar[0];
                a[mt][1] = ar[8 * SK];
                a[mt][2] = ar[4];
                a[mt][3] = ar[8 * SK + 4];
            }
#pragma unroll
            for (int nt = 0; nt < NT; nt++) {
                const uint32_t* br = &Bb[(wn + nt * 8 + gid) * SK + kk + ctg];
                uint32_t b0 = br[0], b1 = br[4];
#pragma unroll
                for (int mt = 0; mt < 2; mt++)
                    mma_tf32(acc[mt][nt][0], acc[mt][nt][1], acc[mt][nt][2], acc[mt][nt][3],
                             a[mt][0], a[mt][1], a[mt][2], a[mt][3], b0, b1);
            }
        }
        __syncthreads();
    }

#pragma unroll
    for (int mt = 0; mt < 2; mt++) {
        int r0 = m0 + wm + mt * 16 + gid;
        int r1 = r0 + 8;
#pragma unroll
        for (int nt = 0; nt < NT; nt++) {
            int col = wn + nt * 8 + 2 * ctg;
            if (r0 < n)
                *(float2*)&Y[(size_t)r0 * O + col] = make_float2(acc[mt][nt][0], acc[mt][nt][1]);
            if (r1 < n)
                *(float2*)&Y[(size_t)r1 * O + col] = make_float2(acc[mt][nt][2], acc[mt][nt][3]);
        }
    }
}

// ---------------- aggregation: out[d] = sum_e w_e * h[src_e] + b ------------
// relu layers also tf32-round the output (it feeds the next GEMM).
__global__ void k_agg128(const float* __restrict__ h, const float* __restrict__ bias,
                         float* __restrict__ out, int n, int relu) {
    int w    = (blockIdx.x * blockDim.x + threadIdx.x) >> 5;
    int lane = threadIdx.x & 31;
    if (w >= n) return;
    const float4* hv = (const float4*)h;
    float4 acc = make_float4(0.f, 0.f, 0.f, 0.f);
    int beg = __ldg(&g_rowptr[w]), end = __ldg(&g_rowptr[w + 1]);

    int e = beg;
    int2 cur[8];
    bool have = (e + 8 <= end);
    if (have) {
#pragma unroll
        for (int j = 0; j < 8; j++) cur[j] = g_cedge[e + j];
    }
    while (have) {
        int en = e + 8;
        bool haven = (en + 8 <= end);
        int2 nxt[8];
        if (haven) {
#pragma unroll
            for (int j = 0; j < 8; j++) nxt[j] = g_cedge[en + j];
        }
#pragma unroll
        for (int j = 0; j < 8; j++) {
            float  ww = __int_as_float(cur[j].y);
            float4 v  = hv[(size_t)cur[j].x * 32 + lane];
            acc.x = fmaf(ww, v.x, acc.x);
            acc.y = fmaf(ww, v.y, acc.y);
            acc.z = fmaf(ww, v.z, acc.z);
            acc.w = fmaf(ww, v.w, acc.w);
        }
        e = en;
        if (haven) {
#pragma unroll
            for (int j = 0; j < 8; j++) cur[j] = nxt[j];
        }
        have = haven;
    }
    for (; e < end; e++) {
        int2 p = g_cedge[e];
        float  ww = __int_as_float(p.y);
        float4 v  = hv[(size_t)p.x * 32 + lane];
        acc.x = fmaf(ww, v.x, acc.x);
        acc.y = fmaf(ww, v.y, acc.y);
        acc.z = fmaf(ww, v.z, acc.z);
        acc.w = fmaf(ww, v.w, acc.w);
    }
    float4 bb = ((const float4*)bias)[lane];
    acc.x += bb.x; acc.y += bb.y; acc.z += bb.z; acc.w += bb.w;
    if (relu) {
        acc.x = rna_tf32(fmaxf(acc.x, 0.f)); acc.y = rna_tf32(fmaxf(acc.y, 0.f));
        acc.z = rna_tf32(fmaxf(acc.z, 0.f)); acc.w = rna_tf32(fmaxf(acc.w, 0.f));
    }
    __stcs(&((float4*)out)[(size_t)w * 32 + lane], acc);
}

__global__ void k_agg64(const float* __restrict__ h, const float* __restrict__ bias,
                        float* __restrict__ out, int n) {
    int w    = (blockIdx.x * blockDim.x + threadIdx.x) >> 5;
    int lane = threadIdx.x & 31;
    if (w >= n) return;
    const float2* hv = (const float2*)h;
    float2 acc = make_float2(0.f, 0.f);
    int beg = __ldg(&g_rowptr[w]), end = __ldg(&g_rowptr[w + 1]);

    int e = beg;
    int2 cur[8];
    bool have = (e + 8 <= end);
    if (have) {
#pragma unroll
        for (int j = 0; j < 8; j++) cur[j] = g_cedge[e + j];
    }
    while (have) {
        int en = e + 8;
        bool haven = (en + 8 <= end);
        int2 nxt[8];
        if (haven) {
#pragma unroll
            for (int j = 0; j < 8; j++) nxt[j] = g_cedge[en + j];
        }
#pragma unroll
        for (int j = 0; j < 8; j++) {
            float  ww = __int_as_float(cur[j].y);
            float2 v  = hv[(size_t)cur[j].x * 32 + lane];
            acc.x = fmaf(ww, v.x, acc.x);
            acc.y = fmaf(ww, v.y, acc.y);
        }
        e = en;
        if (haven) {
#pragma unroll
            for (int j = 0; j < 8; j++) cur[j] = nxt[j];
        }
        have = haven;
    }
    for (; e < end; e++) {
        int2 p = g_cedge[e];
        float  ww = __int_as_float(p.y);
        float2 v  = hv[(size_t)p.x * 32 + lane];
        acc.x = fmaf(ww, v.x, acc.x);
        acc.y = fmaf(ww, v.y, acc.y);
    }
    float2 bb = ((const float2*)bias)[lane];
    acc.x += bb.x; acc.y += bb.y;
    __stcs(&((float2*)out)[(size_t)w * 32 + lane], acc);
}

// ---------------- launch ------------------------------------------------------
extern "C" void kernel_launch(void* const* d_in, const int* in_sizes, int n_in,
                              void* d_out, int out_size) {
    const float* x  = (const float*)d_in[0];
    const int*   ei = (const int*)d_in[1];
    const float* W1 = (const float*)d_in[2];
    const float* b1 = (const float*)d_in[3];
    const float* W2 = (const float*)d_in[4];
    const float* b2 = (const float*)d_in[5];
    const float* W3 = (const float*)d_in[6];
    const float* b3 = (const float*)d_in[7];
    const float* W4 = (const float*)d_in[8];
    const float* b4 = (const float*)d_in[9];

    const int n = in_sizes[0] / KD;       // 100000
    const int E = in_sizes[1] / 2;        // 1600000
    const int* src = ei;
    const int* dst = ei + E;

    float *hA, *hB, *Wr;
    cudaGetSymbolAddress((void**)&hA, g_hA);
    cudaGetSymbolAddress((void**)&hB, g_hB);
    cudaGetSymbolAddress((void**)&Wr, g_Wr);
    const float* W1r = Wr;
    const float* W2r = Wr + 128 * 128;
    const float* W3r = Wr + 2 * 128 * 128;
    const float* W4r = Wr + 3 * 128 * 128;

    const int smem128 = 2 * (128 + 128) * 36 * 4;   // 73728
    const int smem64  = 2 * (128 + 64) * 36 * 4;    // 55296
    cudaFuncSetAttribute(k_mma<128>, cudaFuncAttributeMaxDynamicSharedMemorySize, smem128);
    cudaFuncSetAttribute(k_mma<64>,  cudaFuncAttributeMaxDynamicSharedMemorySize, smem64);

    const int TB = 256;
    int nb_n = (n + TB - 1) / TB;
    int nb_e = (E + TB - 1) / TB;
    int nb_scan = (n + 1023) / 1024;
    int nb_gemm = (n + 127) / 128;
    int nb_agg  = (n * 32 + TB - 1) / TB;
    int m4_x    = n * KD / 4;
    int nb_rx   = (m4_x + TB - 1) / TB;
    int nb_rw   = (3 * 4096 + 2048 + TB - 1) / TB;

    // --- build normalization + CSR (by dst) + tf32 pre-rounding ---
    k_zero   <<<nb_n, TB>>>(n);
    k_deg    <<<nb_e, TB>>>(dst, E);
    k_scan1  <<<nb_scan, 1024>>>(n);
    k_scan2  <<<1, 128>>>(nb_scan);
    k_scan3  <<<nb_n, TB>>>(n);
    k_fill   <<<nb_e, TB>>>(src, dst, E);
    k_round  <<<nb_rx, TB>>>(x, hB, m4_x);          // rounded x -> hB
    k_round_w<<<nb_rw, TB>>>(W1, W2, W3, W4);

    // --- layer 1 ---
    k_mma<128><<<nb_gemm, 256, smem128>>>(hB, W1r, hA, n);
    k_agg128  <<<nb_agg, TB>>>(hA, b1, hB, n, 1);
    // --- layer 2 ---
    k_mma<128><<<nb_gemm, 256, smem128>>>(hB, W2r, hA, n);
    k_agg128  <<<nb_agg, TB>>>(hA, b2, hB, n, 1);
    // --- layer 3 ---
    k_mma<128><<<nb_gemm, 256, smem128>>>(hB, W3r, hA, n);
    k_agg128  <<<nb_agg, TB>>>(hA, b3, hB, n, 1);
    // --- layer 4 ---
    k_mma<64> <<<nb_gemm, 256, smem64>>>(hB, W4r, hA, n);
    k_agg64   <<<nb_agg, TB>>>(hA, b4, (float*)d_out, n);
}

// round 6
// speedup vs baseline: 1.8526x; 1.0042x over previous
#include <cuda_runtime.h>
#include <cstdint>

#define KD 128
#define MAXN 100000
#define MAXE 1600000

// ---------------- device scratch (static; no cudaMalloc) --------------------
static __device__ int   g_deg[MAXN];
static __device__ float g_dinv[MAXN];
static __device__ int   g_rowptr[MAXN + 1];
static __device__ int   g_tmp[MAXN];
static __device__ int   g_bsums[128];
static __device__ int   g_fill[MAXN];
static __device__ int2  g_cedge[MAXE];          // (src, weight-bits)
static __device__ float g_hA[(size_t)MAXN * KD];
static __device__ float g_hB[(size_t)MAXN * KD];
static __device__ float g_Wr[3 * 128 * 128 + 64 * 128];   // tf32-rounded W1..W4

// ---------------- tf32 helpers ----------------------------------------------
__device__ __forceinline__ float rna_tf32(float f) {
    uint32_t r;
    asm("cvt.rna.tf32.f32 %0, %1;" : "=r"(r) : "f"(f));
    return __uint_as_float(r);
}

// ---------------- cp.async helpers ------------------------------------------
__device__ __forceinline__ void cpa16(uint32_t saddr, const void* gaddr, uint32_t ssz) {
    asm volatile("cp.async.cg.shared.global [%0], [%1], 16, %2;"
                 :: "r"(saddr), "l"(gaddr), "r"(ssz) : "memory");
}
#define CP_COMMIT()  asm volatile("cp.async.commit_group;" ::: "memory")
#define CP_WAIT1()   asm volatile("cp.async.wait_group 1;" ::: "memory")
#define CP_WAIT0()   asm volatile("cp.async.wait_group 0;" ::: "memory")

// ---------------- preprocessing kernels -------------------------------------
__global__ void k_zero(int n) {
    int i = blockIdx.x * blockDim.x + threadIdx.x;
    if (i < n) { g_deg[i] = 0; g_fill[i] = 0; }
}
__global__ void k_deg(const int* __restrict__ dst, int E) {
    int e = blockIdx.x * blockDim.x + threadIdx.x;
    if (e < E) atomicAdd(&g_deg[dst[e]], 1);
}
__global__ void k_scan1(int n) {
    __shared__ int s[1024];
    int t = threadIdx.x;
    int i = blockIdx.x * 1024 + t;
    int v = (i < n) ? g_deg[i] : 0;
    s[t] = v;
    __syncthreads();
    for (int off = 1; off < 1024; off <<= 1) {
        int x = (t >= off) ? s[t - off] : 0;
        __syncthreads();
        s[t] += x;
        __syncthreads();
    }
    if (i < n) g_tmp[i] = s[t];
    if (t == 1023) g_bsums[blockIdx.x] = s[t];
}
__global__ void k_scan2(int nb) {
    __shared__ int s[128];
    int t = threadIdx.x;
    int v = (t < nb) ? g_bsums[t] : 0;
    s[t] = v;
    __syncthreads();
    for (int off = 1; off < 128; off <<= 1) {
        int x = (t >= off) ? s[t - off] : 0;
        __syncthreads();
        s[t] += x;
        __syncthreads();
    }
    if (t < nb) g_bsums[t] = s[t] - v;
}
__global__ void k_scan3(int n) {            // also computes dinv
    int i = blockIdx.x * blockDim.x + threadIdx.x;
    if (i < n) {
        g_rowptr[i + 1] = g_tmp[i] + g_bsums[i >> 10];
        if (i == 0) g_rowptr[0] = 0;
        int d = g_deg[i];
        g_dinv[i] = (d > 0) ? rsqrtf((float)d) : 0.f;
    }
}
__global__ void k_fill(const int* __restrict__ src, const int* __restrict__ dst, int E) {
    int e = blockIdx.x * blockDim.x + threadIdx.x;
    if (e < E) {
        int s = src[e], d = dst[e];
        int pos = g_rowptr[d] + atomicAdd(&g_fill[d], 1);
        g_cedge[pos] = make_int2(s, __float_as_int(g_dinv[s] * g_dinv[d]));
    }
}

// elementwise tf32 rounding pass (vectorized)
__global__ void k_round(const float* __restrict__ in, float* __restrict__ out, int m4) {
    int i = blockIdx.x * blockDim.x + threadIdx.x;
    if (i < m4) {
        float4 v = ((const float4*)in)[i];
        v.x = rna_tf32(v.x); v.y = rna_tf32(v.y);
        v.z = rna_tf32(v.z); v.w = rna_tf32(v.w);
        ((float4*)out)[i] = v;
    }
}

// round all 4 weight matrices into g_Wr
__global__ void k_round_w(const float* __restrict__ W1, const float* __restrict__ W2,
                          const float* __restrict__ W3, const float* __restrict__ W4) {
    int i = blockIdx.x * blockDim.x + threadIdx.x;     // float4 index
    const int S = 128 * 128 / 4;
    const float4* src;
    int off;
    if      (i < S)     { src = (const float4*)W1; off = 0;     }
    else if (i < 2 * S) { src = (const float4*)W2; off = S;     i -= S; }
    else if (i < 3 * S) { src = (const float4*)W3; off = 2 * S; i -= 2 * S; }
    else if (i < 3 * S + S / 2) { src = (const float4*)W4; off = 3 * S; i -= 3 * S; }
    else return;
    float4 v = src[i];
    v.x = rna_tf32(v.x); v.y = rna_tf32(v.y);
    v.z = rna_tf32(v.z); v.w = rna_tf32(v.w);
    ((float4*)g_Wr)[off + i] = v;
}

// ---------------- tf32 mma.sync GEMM, cp.async double-buffered --------------
__device__ __forceinline__ void mma_tf32(float& d0, float& d1, float& d2, float& d3,
                                         uint32_t a0, uint32_t a1, uint32_t a2, uint32_t a3,
                                         uint32_t b0, uint32_t b1) {
    asm volatile(
        "mma.sync.aligned.m16n8k8.row.col.f32.tf32.tf32.f32 "
        "{%0,%1,%2,%3}, {%4,%5,%6,%7}, {%8,%9}, {%0,%1,%2,%3};"
        : "+f"(d0), "+f"(d1), "+f"(d2), "+f"(d3)
        : "r"(a0), "r"(a1), "r"(a2), "r"(a3), "r"(b0), "r"(b1));
}

template <int O>
__global__ void __launch_bounds__(256, 2) k_mma(const float* __restrict__ X,
                                                const float* __restrict__ W,
                                                float* __restrict__ Y, int n) {
    constexpr int SK = 36;               // 32 + 4 pad
    constexpr int NT = (O / 2) / 8;
    extern __shared__ float sm[];
    float* As = sm;                      // [2][128*SK]
    float* Bs = sm + 2 * 128 * SK;       // [2][O*SK]
    const uint32_t sA = (uint32_t)__cvta_generic_to_shared(As);
    const uint32_t sB = (uint32_t)__cvta_generic_to_shared(Bs);

    const int tid = threadIdx.x;
    const int m0  = blockIdx.x * 128;

    auto load_chunk = [&](int c, int buf) {
        for (int idx = tid; idx < 128 * 8; idx += 256) {
            int row = idx >> 3, seg = idx & 7;
            uint32_t sa = sA + (uint32_t)((buf * 128 * SK + row * SK + seg * 4) * 4);
            int grow = (m0 + row < n) ? (m0 + row) : 0;
            const float* g = X + (size_t)grow * 128 + c * 32 + seg * 4;
            cpa16(sa, g, (m0 + row < n) ? 16u : 0u);
        }
        for (int idx = tid; idx < O * 8; idx += 256) {
            int row = idx >> 3, seg = idx & 7;
            uint32_t sa = sB + (uint32_t)((buf * O * SK + row * SK + seg * 4) * 4);
            const float* g = W + (size_t)row * 128 + c * 32 + seg * 4;
            cpa16(sa, g, 16u);
        }
        CP_COMMIT();
    };

    const int wid  = tid >> 5;
    const int lane = tid & 31;
    const int wm   = (wid & 3) * 32;
    const int wn   = (wid >> 2) * (O / 2);
    const int gid  = lane >> 2;
    const int ctg  = lane & 3;

    float acc[2][NT][4];
#pragma unroll
    for (int i = 0; i < 2; i++)
#pragma unroll
        for (int j = 0; j < NT; j++)
#pragma unroll
            for (int c = 0; c < 4; c++) acc[i][j][c] = 0.f;

    load_chunk(0, 0);

#pragma unroll
    for (int c = 0; c < 4; c++) {
        if (c < 3) { load_chunk(c + 1, (c + 1) & 1); CP_WAIT1(); }
        else       { CP_WAIT0(); }
        __syncthreads();

        const uint32_t* Ab = (const uint32_t*)(As + (c & 1) * 128 * SK);
        const uint32_t* Bb = (const uint32_t*)(Bs + (c & 1) * O * SK);
#pragma unroll
        for (int kk = 0; kk < 32; kk += 8) {
            uint32_t a[2][4];
#pragma unroll
            for (int mt = 0; mt < 2; mt++) {
                const uint32_t* ar = &Ab[(wm + mt * 16 + gid) * SK + kk + ctg];
                a[mt][0] = ar[0];
                a[mt][1] = ar[8 * SK];
                a[mt][2] = ar[4];
                a[mt][3] = ar[8 * SK + 4];
            }
#pragma unroll
            for (int nt = 0; nt < NT; nt++) {
                const uint32_t* br = &Bb[(wn + nt * 8 + gid) * SK + kk + ctg];
                uint32_t b0 = br[0], b1 = br[4];
#pragma unroll
                for (int mt = 0; mt < 2; mt++)
                    mma_tf32(acc[mt][nt][0], acc[mt][nt][1], acc[mt][nt][2], acc[mt][nt][3],
                             a[mt][0], a[mt][1], a[mt][2], a[mt][3], b0, b1);
            }
        }
        __syncthreads();
    }

#pragma unroll
    for (int mt = 0; mt < 2; mt++) {
        int r0 = m0 + wm + mt * 16 + gid;
        int r1 = r0 + 8;
#pragma unroll
        for (int nt = 0; nt < NT; nt++) {
            int col = wn + nt * 8 + 2 * ctg;
            if (r0 < n)
                *(float2*)&Y[(size_t)r0 * O + col] = make_float2(acc[mt][nt][0], acc[mt][nt][1]);
            if (r1 < n)
                *(float2*)&Y[(size_t)r1 * O + col] = make_float2(acc[mt][nt][2], acc[mt][nt][3]);
        }
    }
}

// ---------------- aggregation: out[d] = sum_e w_e * h[src_e] + b ------------
// one warp per node. Edge records for 32 edges are fetched by ONE coalesced
// per-lane int2 load and broadcast via shfl -> record loads leave the critical
// path; gathers issue in unrolled groups of 8 (MLP=8).
__global__ void k_agg128(const float* __restrict__ h, const float* __restrict__ bias,
                         float* __restrict__ out, int n, int relu) {
    int w    = (blockIdx.x * blockDim.x + threadIdx.x) >> 5;
    int lane = threadIdx.x & 31;
    if (w >= n) return;
    const float4* hv = (const float4*)h;
    float4 acc = make_float4(0.f, 0.f, 0.f, 0.f);
    int beg = __ldg(&g_rowptr[w]), end = __ldg(&g_rowptr[w + 1]);

    for (int base = beg; base < end; base += 32) {
        int cnt = end - base;
        if (cnt > 32) cnt = 32;
        int2 rec = make_int2(0, 0);
        if (lane < cnt) rec = __ldg(&g_cedge[base + lane]);
        int j = 0;
        for (; j + 8 <= cnt; j += 8) {
            int   s[8];
            float wv[8];
#pragma unroll
            for (int k = 0; k < 8; k++) {
                s[k]  = __shfl_sync(0xFFFFFFFFu, rec.x, j + k);
                wv[k] = __int_as_float(__shfl_sync(0xFFFFFFFFu, rec.y, j + k));
            }
            float4 v[8];
#pragma unroll
            for (int k = 0; k < 8; k++) v[k] = hv[(size_t)s[k] * 32 + lane];
#pragma unroll
            for (int k = 0; k < 8; k++) {
                acc.x = fmaf(wv[k], v[k].x, acc.x);
                acc.y = fmaf(wv[k], v[k].y, acc.y);
                acc.z = fmaf(wv[k], v[k].z, acc.z);
                acc.w = fmaf(wv[k], v[k].w, acc.w);
            }
        }
        for (; j < cnt; j++) {
            int   s  = __shfl_sync(0xFFFFFFFFu, rec.x, j);
            float ww = __int_as_float(__shfl_sync(0xFFFFFFFFu, rec.y, j));
            float4 v = hv[(size_t)s * 32 + lane];
            acc.x = fmaf(ww, v.x, acc.x);
            acc.y = fmaf(ww, v.y, acc.y);
            acc.z = fmaf(ww, v.z, acc.z);
            acc.w = fmaf(ww, v.w, acc.w);
        }
    }
    float4 bb = ((const float4*)bias)[lane];
    acc.x += bb.x; acc.y += bb.y; acc.z += bb.z; acc.w += bb.w;
    if (relu) {
        acc.x = rna_tf32(fmaxf(acc.x, 0.f)); acc.y = rna_tf32(fmaxf(acc.y, 0.f));
        acc.z = rna_tf32(fmaxf(acc.z, 0.f)); acc.w = rna_tf32(fmaxf(acc.w, 0.f));
    }
    __stcs(&((float4*)out)[(size_t)w * 32 + lane], acc);
}

__global__ void k_agg64(const float* __restrict__ h, const float* __restrict__ bias,
                        float* __restrict__ out, int n) {
    int w    = (blockIdx.x * blockDim.x + threadIdx.x) >> 5;
    int lane = threadIdx.x & 31;
    if (w >= n) return;
    const float2* hv = (const float2*)h;
    float2 acc = make_float2(0.f, 0.f);
    int beg = __ldg(&g_rowptr[w]), end = __ldg(&g_rowptr[w + 1]);

    for (int base = beg; base < end; base += 32) {
        int cnt = end - base;
        if (cnt > 32) cnt = 32;
        int2 rec = make_int2(0, 0);
        if (lane < cnt) rec = __ldg(&g_cedge[base + lane]);
        int j = 0;
        for (; j + 8 <= cnt; j += 8) {
            int   s[8];
            float wv[8];
#pragma unroll
            for (int k = 0; k < 8; k++) {
                s[k]  = __shfl_sync(0xFFFFFFFFu, rec.x, j + k);
                wv[k] = __int_as_float(__shfl_sync(0xFFFFFFFFu, rec.y, j + k));
            }
            float2 v[8];
#pragma unroll
            for (int k = 0; k < 8; k++) v[k] = hv[(size_t)s[k] * 32 + lane];
#pragma unroll
            for (int k = 0; k < 8; k++) {
                acc.x = fmaf(wv[k], v[k].x, acc.x);
                acc.y = fmaf(wv[k], v[k].y, acc.y);
            }
        }
        for (; j < cnt; j++) {
            int   s  = __shfl_sync(0xFFFFFFFFu, rec.x, j);
            float ww = __int_as_float(__shfl_sync(0xFFFFFFFFu, rec.y, j));
            float2 v = hv[(size_t)s * 32 + lane];
            acc.x = fmaf(ww, v.x, acc.x);
            acc.y = fmaf(ww, v.y, acc.y);
        }
    }
    float2 bb = ((const float2*)bias)[lane];
    acc.x += bb.x; acc.y += bb.y;
    __stcs(&((float2*)out)[(size_t)w * 32 + lane], acc);
}

// ---------------- launch ------------------------------------------------------
extern "C" void kernel_launch(void* const* d_in, const int* in_sizes, int n_in,
                              void* d_out, int out_size) {
    const float* x  = (const float*)d_in[0];
    const int*   ei = (const int*)d_in[1];
    const float* W1 = (const float*)d_in[2];
    const float* b1 = (const float*)d_in[3];
    const float* W2 = (const float*)d_in[4];
    const float* b2 = (const float*)d_in[5];
    const float* W3 = (const float*)d_in[6];
    const float* b3 = (const float*)d_in[7];
    const float* W4 = (const float*)d_in[8];
    const float* b4 = (const float*)d_in[9];

    const int n = in_sizes[0] / KD;       // 100000
    const int E = in_sizes[1] / 2;        // 1600000
    const int* src = ei;
    const int* dst = ei + E;

    float *hA, *hB, *Wr;
    cudaGetSymbolAddress((void**)&hA, g_hA);
    cudaGetSymbolAddress((void**)&hB, g_hB);
    cudaGetSymbolAddress((void**)&Wr, g_Wr);
    const float* W1r = Wr;
    const float* W2r = Wr + 128 * 128;
    const float* W3r = Wr + 2 * 128 * 128;
    const float* W4r = Wr + 3 * 128 * 128;

    const int smem128 = 2 * (128 + 128) * 36 * 4;   // 73728
    const int smem64  = 2 * (128 + 64) * 36 * 4;    // 55296
    cudaFuncSetAttribute(k_mma<128>, cudaFuncAttributeMaxDynamicSharedMemorySize, smem128);
    cudaFuncSetAttribute(k_mma<64>,  cudaFuncAttributeMaxDynamicSharedMemorySize, smem64);

    const int TB = 256;
    int nb_n = (n + TB - 1) / TB;
    int nb_e = (E + TB - 1) / TB;
    int nb_scan = (n + 1023) / 1024;
    int nb_gemm = (n + 127) / 128;
    int nb_agg  = (n * 32 + TB - 1) / TB;
    int m4_x    = n * KD / 4;
    int nb_rx   = (m4_x + TB - 1) / TB;
    int nb_rw   = (3 * 4096 + 2048 + TB - 1) / TB;

    // Launch order puts mma1 at index 3 (observed ncu capture slot) so the
    // next profile lands on the GEMM instead of a tiny scan kernel.
    k_round  <<<nb_rx, TB>>>(x, hB, m4_x);          // 0: rounded x -> hB
    k_round_w<<<nb_rw, TB>>>(W1, W2, W3, W4);       // 1
    k_zero   <<<nb_n, TB>>>(n);                     // 2
    k_mma<128><<<nb_gemm, 256, smem128>>>(hB, W1r, hA, n);   // 3: layer-1 GEMM
    // --- CSR build (needed before agg1) ---
    k_deg    <<<nb_e, TB>>>(dst, E);                // 4
    k_scan1  <<<nb_scan, 1024>>>(n);                // 5
    k_scan2  <<<1, 128>>>(nb_scan);                 // 6
    k_scan3  <<<nb_n, TB>>>(n);                     // 7
    k_fill   <<<nb_e, TB>>>(src, dst, E);           // 8

    // --- layer 1 agg ---
    k_agg128  <<<nb_agg, TB>>>(hA, b1, hB, n, 1);
    // --- layer 2 ---
    k_mma<128><<<nb_gemm, 256, smem128>>>(hB, W2r, hA, n);
    k_agg128  <<<nb_agg, TB>>>(hA, b2, hB, n, 1);
    // --- layer 3 ---
    k_mma<128><<<nb_gemm, 256, smem128>>>(hB, W3r, hA, n);
    k_agg128  <<<nb_agg, TB>>>(hA, b3, hB, n, 1);
    // --- layer 4 ---
    k_mma<64> <<<nb_gemm, 256, smem64>>>(hB, W4r, hA, n);
    k_agg64   <<<nb_agg, TB>>>(hA, b4, (float*)d_out, n);
}